// round 1
// baseline (speedup 1.0000x reference)
#include <cuda_runtime.h>
#include <mma.h>
#include <cstdint>

using namespace nvcuda;

#define D_MODEL 768
#define HEADS   12
#define D_HEAD  64
#define NB      16
#define SP      256
#define SI      1024
#define TOKP    (NB*SP)     /* 4096  */
#define TOKI    (NB*SI)     /* 16384 */

// ---------------- scratch (device globals: no allocations allowed) ----------------
__device__ float g_prompt0[TOKP*D_MODEL];
__device__ float g_x      [TOKP*D_MODEL];
__device__ float g_xi     [TOKI*D_MODEL];
__device__ float g_q      [TOKP*D_MODEL];
__device__ float g_k      [TOKI*D_MODEL];
__device__ float g_v      [TOKI*D_MODEL];
__device__ float g_scores [(size_t)NB*HEADS*SP*SI];
__device__ float g_attn   [TOKP*D_MODEL];
__device__ float g_p1     [TOKP*D_MODEL];
__device__ float g_p2     [TOKP*D_MODEL];
__device__ float g_h      [TOKP*D_MODEL];

// ---------------- elementwise add (float4) ----------------
__global__ void add4_kernel(const float4* __restrict__ a, const float4* __restrict__ b,
                            float4* __restrict__ o, int n4) {
    int i = blockIdx.x * blockDim.x + threadIdx.x;
    if (i < n4) {
        float4 x = a[i], y = b[i];
        x.x += y.x; x.y += y.y; x.z += y.z; x.w += y.w;
        o[i] = x;
    }
}

// ---------------- (optional add) + layernorm, one row (768) per block of 256 ----------------
__global__ void addln_kernel(const float* __restrict__ a, const float* __restrict__ b,
                             const float* __restrict__ g, const float* __restrict__ be,
                             float* __restrict__ o) {
    int row = blockIdx.x;
    const float* pa = a + (size_t)row * D_MODEL;
    const float* pb = b ? b + (size_t)row * D_MODEL : nullptr;
    float x[3];
    float s = 0.f, sq = 0.f;
#pragma unroll
    for (int j = 0; j < 3; j++) {
        int i = threadIdx.x + j * 256;
        float v = pa[i];
        if (pb) v += pb[i];
        x[j] = v; s += v; sq += v * v;
    }
    __shared__ float sb[16];
    unsigned wid = threadIdx.x >> 5, lane = threadIdx.x & 31;
#pragma unroll
    for (int off = 16; off; off >>= 1) {
        s  += __shfl_xor_sync(0xffffffffu, s,  off);
        sq += __shfl_xor_sync(0xffffffffu, sq, off);
    }
    if (lane == 0) { sb[wid] = s; sb[8 + wid] = sq; }
    __syncthreads();
    if (threadIdx.x < 32) {
        float s2 = (lane < 8) ? sb[lane] : 0.f;
        float q2 = (lane < 8) ? sb[8 + lane] : 0.f;
#pragma unroll
        for (int off = 4; off; off >>= 1) {
            s2 += __shfl_xor_sync(0xffffffffu, s2, off);
            q2 += __shfl_xor_sync(0xffffffffu, q2, off);
        }
        if (lane == 0) { sb[0] = s2; sb[1] = q2; }
    }
    __syncthreads();
    float mean = sb[0] * (1.f / 768.f);
    float var  = sb[1] * (1.f / 768.f) - mean * mean;
    float rs   = rsqrtf(var + 1e-5f);
    float* po = o + (size_t)row * D_MODEL;
#pragma unroll
    for (int j = 0; j < 3; j++) {
        int i = threadIdx.x + j * 256;
        po[i] = (x[j] - mean) * rs * g[i] + be[i];
    }
}

// ---------------- row softmax, PER = len/256 elements per thread ----------------
template <int PER>
__global__ void softmax_kernel(float* __restrict__ S, int len) {
    size_t row = blockIdx.x;
    float* p = S + row * (size_t)len;
    float v[PER];
    float mx = -3.0e38f;
#pragma unroll
    for (int j = 0; j < PER; j++) {
        v[j] = p[threadIdx.x + j * 256];
        mx = fmaxf(mx, v[j]);
    }
    __shared__ float sb[9];
    unsigned wid = threadIdx.x >> 5, lane = threadIdx.x & 31;
#pragma unroll
    for (int off = 16; off; off >>= 1) mx = fmaxf(mx, __shfl_xor_sync(0xffffffffu, mx, off));
    if (lane == 0) sb[wid] = mx;
    __syncthreads();
    if (threadIdx.x < 32) {
        float m = (lane < 8) ? sb[lane] : -3.0e38f;
#pragma unroll
        for (int off = 4; off; off >>= 1) m = fmaxf(m, __shfl_xor_sync(0xffffffffu, m, off));
        if (lane == 0) sb[8] = m;
    }
    __syncthreads();
    mx = sb[8];
    float sum = 0.f;
#pragma unroll
    for (int j = 0; j < PER; j++) { v[j] = expf(v[j] - mx); sum += v[j]; }
    __syncthreads();  // sb reuse
#pragma unroll
    for (int off = 16; off; off >>= 1) sum += __shfl_xor_sync(0xffffffffu, sum, off);
    if (lane == 0) sb[wid] = sum;
    __syncthreads();
    if (threadIdx.x < 32) {
        float m = (lane < 8) ? sb[lane] : 0.f;
#pragma unroll
        for (int off = 4; off; off >>= 1) m += __shfl_xor_sync(0xffffffffu, m, off);
        if (lane == 0) sb[8] = m;
    }
    __syncthreads();
    float inv = 1.f / sb[8];
#pragma unroll
    for (int j = 0; j < PER; j++) p[threadIdx.x + j * 256] = v[j] * inv;
}

// ---------------- TF32 wmma GEMM, 128x64 tile, 256 thr (8 warps, each 32x32) ----------------
#define GBM 128
#define GBN 64
#define GBK 32
#define ALD 36   /* smem ld for [*,32] tiles */
#define BLD 68   /* smem ld for [*,64] tiles */
#define CLD 68

using FragA  = wmma::fragment<wmma::matrix_a, 16, 16, 8, wmma::precision::tf32, wmma::row_major>;
using FragB  = wmma::fragment<wmma::matrix_b, 16, 16, 8, wmma::precision::tf32, wmma::row_major>;
using FragBT = wmma::fragment<wmma::matrix_b, 16, 16, 8, wmma::precision::tf32, wmma::col_major>;
using FragC  = wmma::fragment<wmma::accumulator, 16, 16, 8, float>;

// C[M,N] = A[M,K] @ W[K,N] + bias (+ resid) (relu?)   all fp32, tf32 tensor cores
__global__ __launch_bounds__(256) void gemm_bias_kernel(
    const float* __restrict__ A, const float* __restrict__ W,
    const float* __restrict__ bias, const float* __restrict__ resid,
    float* __restrict__ C, int M, int N, int K, int relu) {
    __shared__ __align__(16) float sm[GBM * CLD];  // 8704 floats; union of load/epilogue stages
    float* As = sm;              // [128][36]
    float* Bs = sm + GBM * ALD;  // [32][68]
    int tid = threadIdx.x;
    int m0 = blockIdx.y * GBM, n0 = blockIdx.x * GBN;
    int warp = tid >> 5, wm = warp & 3, wn = warp >> 2;

    FragC acc[2][2];
#pragma unroll
    for (int i = 0; i < 2; i++)
#pragma unroll
        for (int j = 0; j < 2; j++) wmma::fill_fragment(acc[i][j], 0.f);

    for (int k0 = 0; k0 < K; k0 += GBK) {
#pragma unroll
        for (int i = 0; i < 4; i++) {
            int p = tid + i * 256, r = p >> 3, c = (p & 7) * 4;
            *(float4*)&As[r * ALD + c] = *(const float4*)&A[(size_t)(m0 + r) * K + k0 + c];
        }
#pragma unroll
        for (int i = 0; i < 2; i++) {
            int p = tid + i * 256, r = p >> 4, c = (p & 15) * 4;
            *(float4*)&Bs[r * BLD + c] = *(const float4*)&W[(size_t)(k0 + r) * N + n0 + c];
        }
        __syncthreads();
#pragma unroll
        for (int kk = 0; kk < GBK; kk += 8) {
            FragA fa[2]; FragB fb[2];
#pragma unroll
            for (int i = 0; i < 2; i++) {
                wmma::load_matrix_sync(fa[i], &As[(wm * 32 + i * 16) * ALD + kk], ALD);
#pragma unroll
                for (int t = 0; t < fa[i].num_elements; t++) fa[i].x[t] = wmma::__float_to_tf32(fa[i].x[t]);
            }
#pragma unroll
            for (int j = 0; j < 2; j++) {
                wmma::load_matrix_sync(fb[j], &Bs[kk * BLD + wn * 32 + j * 16], BLD);
#pragma unroll
                for (int t = 0; t < fb[j].num_elements; t++) fb[j].x[t] = wmma::__float_to_tf32(fb[j].x[t]);
            }
#pragma unroll
            for (int i = 0; i < 2; i++)
#pragma unroll
                for (int j = 0; j < 2; j++) wmma::mma_sync(acc[i][j], fa[i], fb[j], acc[i][j]);
        }
        __syncthreads();
    }
    // epilogue via smem staging
    float* Cs = sm;
#pragma unroll
    for (int i = 0; i < 2; i++)
#pragma unroll
        for (int j = 0; j < 2; j++)
            wmma::store_matrix_sync(&Cs[(wm * 32 + i * 16) * CLD + wn * 32 + j * 16], acc[i][j], CLD, wmma::mem_row_major);
    __syncthreads();
#pragma unroll
    for (int i = 0; i < 8; i++) {
        int p = tid + i * 256, r = p >> 4, c = (p & 15) * 4;
        float4 v = *(float4*)&Cs[r * CLD + c];
        int gc = n0 + c;
        float4 bv = *(const float4*)&bias[gc];
        v.x += bv.x; v.y += bv.y; v.z += bv.z; v.w += bv.w;
        size_t off = (size_t)(m0 + r) * N + gc;
        if (resid) {
            float4 rv = *(const float4*)&resid[off];
            v.x += rv.x; v.y += rv.y; v.z += rv.z; v.w += rv.w;
        }
        if (relu) {
            v.x = fmaxf(v.x, 0.f); v.y = fmaxf(v.y, 0.f);
            v.z = fmaxf(v.z, 0.f); v.w = fmaxf(v.w, 0.f);
        }
        *(float4*)&C[off] = v;
    }
}

// ---------------- batched strided GEMM (attention). BT: C = A @ B^T ----------------
template <bool BT>
__global__ __launch_bounds__(256) void bgemm_kernel(
    const float* __restrict__ A, int lda, long sAb, long sAh,
    const float* __restrict__ Bm, int ldb, long sBb, long sBh,
    float* __restrict__ C, int ldc, long sCb, long sCh,
    int M, int N, int K, float alpha) {
    int z = blockIdx.z, bi = z / HEADS, hi = z % HEADS;
    const float* Ab = A  + (size_t)bi * sAb + (size_t)hi * sAh;
    const float* Bb = Bm + (size_t)bi * sBb + (size_t)hi * sBh;
    float*       Cb = C  + (size_t)bi * sCb + (size_t)hi * sCh;

    __shared__ __align__(16) float sm[GBM * CLD];
    float* As = sm;              // [128][36]
    float* Bs = sm + GBM * ALD;  // BT: [64][36]  else [32][68]
    int tid = threadIdx.x;
    int m0 = blockIdx.y * GBM, n0 = blockIdx.x * GBN;
    int warp = tid >> 5, wm = warp & 3, wn = warp >> 2;

    FragC acc[2][2];
#pragma unroll
    for (int i = 0; i < 2; i++)
#pragma unroll
        for (int j = 0; j < 2; j++) wmma::fill_fragment(acc[i][j], 0.f);

    for (int k0 = 0; k0 < K; k0 += GBK) {
#pragma unroll
        for (int i = 0; i < 4; i++) {
            int p = tid + i * 256, r = p >> 3, c = (p & 7) * 4;
            *(float4*)&As[r * ALD + c] = *(const float4*)&Ab[(size_t)(m0 + r) * lda + k0 + c];
        }
        if (BT) {
#pragma unroll
            for (int i = 0; i < 2; i++) {
                int p = tid + i * 256, r = p >> 3, c = (p & 7) * 4;  // r<64, 32-wide
                *(float4*)&Bs[r * ALD + c] = *(const float4*)&Bb[(size_t)(n0 + r) * ldb + k0 + c];
            }
        } else {
#pragma unroll
            for (int i = 0; i < 2; i++) {
                int p = tid + i * 256, r = p >> 4, c = (p & 15) * 4;  // r<32, 64-wide
                *(float4*)&Bs[r * BLD + c] = *(const float4*)&Bb[(size_t)(k0 + r) * ldb + n0 + c];
            }
        }
        __syncthreads();
#pragma unroll
        for (int kk = 0; kk < GBK; kk += 8) {
            FragA fa[2];
#pragma unroll
            for (int i = 0; i < 2; i++) {
                wmma::load_matrix_sync(fa[i], &As[(wm * 32 + i * 16) * ALD + kk], ALD);
#pragma unroll
                for (int t = 0; t < fa[i].num_elements; t++) fa[i].x[t] = wmma::__float_to_tf32(fa[i].x[t]);
            }
            if (BT) {
                FragBT fb[2];
#pragma unroll
                for (int j = 0; j < 2; j++) {
                    wmma::load_matrix_sync(fb[j], &Bs[(wn * 32 + j * 16) * ALD + kk], ALD);
#pragma unroll
                    for (int t = 0; t < fb[j].num_elements; t++) fb[j].x[t] = wmma::__float_to_tf32(fb[j].x[t]);
                }
#pragma unroll
                for (int i = 0; i < 2; i++)
#pragma unroll
                    for (int j = 0; j < 2; j++) wmma::mma_sync(acc[i][j], fa[i], fb[j], acc[i][j]);
            } else {
                FragB fb[2];
#pragma unroll
                for (int j = 0; j < 2; j++) {
                    wmma::load_matrix_sync(fb[j], &Bs[kk * BLD + wn * 32 + j * 16], BLD);
#pragma unroll
                    for (int t = 0; t < fb[j].num_elements; t++) fb[j].x[t] = wmma::__float_to_tf32(fb[j].x[t]);
                }
#pragma unroll
                for (int i = 0; i < 2; i++)
#pragma unroll
                    for (int j = 0; j < 2; j++) wmma::mma_sync(acc[i][j], fa[i], fb[j], acc[i][j]);
            }
        }
        __syncthreads();
    }
    float* Cs = sm;
#pragma unroll
    for (int i = 0; i < 2; i++)
#pragma unroll
        for (int j = 0; j < 2; j++)
            wmma::store_matrix_sync(&Cs[(wm * 32 + i * 16) * CLD + wn * 32 + j * 16], acc[i][j], CLD, wmma::mem_row_major);
    __syncthreads();
#pragma unroll
    for (int i = 0; i < 8; i++) {
        int p = tid + i * 256, r = p >> 4, c = (p & 15) * 4;
        float4 v = *(float4*)&Cs[r * CLD + c];
        v.x *= alpha; v.y *= alpha; v.z *= alpha; v.w *= alpha;
        *(float4*)&Cb[(size_t)(m0 + r) * ldc + n0 + c] = v;
    }
}

// ---------------- launcher ----------------
extern "C" void kernel_launch(void* const* d_in, const int* in_sizes, int n_in,
                              void* d_out, int out_size) {
    (void)in_sizes; (void)n_in; (void)out_size;
    const float* image  = (const float*)d_in[0];
    const float* prompt = (const float*)d_in[1];
    const float* posi   = (const float*)d_in[2];
    const float* posp   = (const float*)d_in[3];
    const float* ln1g = (const float*)d_in[4],  *ln1b = (const float*)d_in[5];
    const float* ln2g = (const float*)d_in[6],  *ln2b = (const float*)d_in[7];
    const float* ln3g = (const float*)d_in[8],  *ln3b = (const float*)d_in[9];
    const float* lnig = (const float*)d_in[10], *lnib = (const float*)d_in[11];
    const float* pp_wq = (const float*)d_in[12], *pp_bq = (const float*)d_in[13];
    const float* pp_wk = (const float*)d_in[14], *pp_bk = (const float*)d_in[15];
    const float* pp_wv = (const float*)d_in[16], *pp_bv = (const float*)d_in[17];
    const float* pp_wo = (const float*)d_in[18], *pp_bo = (const float*)d_in[19];
    const float* pi_wq = (const float*)d_in[20], *pi_bq = (const float*)d_in[21];
    const float* pi_wk = (const float*)d_in[22], *pi_bk = (const float*)d_in[23];
    const float* pi_wv = (const float*)d_in[24], *pi_bv = (const float*)d_in[25];
    const float* pi_wo = (const float*)d_in[26], *pi_bo = (const float*)d_in[27];
    const float* ff_w1 = (const float*)d_in[28], *ff_b1 = (const float*)d_in[29];
    const float* ff_w2 = (const float*)d_in[30], *ff_b2 = (const float*)d_in[31];
    float* out = (float*)d_out;

    float *prompt0, *x, *xi, *q, *k, *v, *sc, *attn, *p1, *p2, *hbuf;
    cudaGetSymbolAddress((void**)&prompt0, g_prompt0);
    cudaGetSymbolAddress((void**)&x,       g_x);
    cudaGetSymbolAddress((void**)&xi,      g_xi);
    cudaGetSymbolAddress((void**)&q,       g_q);
    cudaGetSymbolAddress((void**)&k,       g_k);
    cudaGetSymbolAddress((void**)&v,       g_v);
    cudaGetSymbolAddress((void**)&sc,      g_scores);
    cudaGetSymbolAddress((void**)&attn,    g_attn);
    cudaGetSymbolAddress((void**)&p1,      g_p1);
    cudaGetSymbolAddress((void**)&p2,      g_p2);
    cudaGetSymbolAddress((void**)&hbuf,    g_h);

    const dim3 gp(D_MODEL / GBN, TOKP / GBM);   // (12, 32)
    const dim3 gi(D_MODEL / GBN, TOKI / GBM);   // (12, 128)

    // 1. prompt0 = prompt + posp
    add4_kernel<<<(TOKP * D_MODEL / 4 + 255) / 256, 256>>>(
        (const float4*)prompt, (const float4*)posp, (float4*)prompt0, TOKP * D_MODEL / 4);
    // 2. x = LN(prompt0)
    addln_kernel<<<TOKP, 256>>>(prompt0, nullptr, ln1g, ln1b, x);
    // 3-5. self-attn QKV
    gemm_bias_kernel<<<gp, 256>>>(x, pp_wq, pp_bq, nullptr, q, TOKP, D_MODEL, D_MODEL, 0);
    gemm_bias_kernel<<<gp, 256>>>(x, pp_wk, pp_bk, nullptr, k, TOKP, D_MODEL, D_MODEL, 0);
    gemm_bias_kernel<<<gp, 256>>>(x, pp_wv, pp_bv, nullptr, v, TOKP, D_MODEL, D_MODEL, 0);
    // 6. scores = Q @ K^T / 8
    {
        dim3 gs(SP / GBN, SP / GBM, NB * HEADS);
        bgemm_kernel<true><<<gs, 256>>>(q, D_MODEL, (long)SP * D_MODEL, D_HEAD,
                                        k, D_MODEL, (long)SP * D_MODEL, D_HEAD,
                                        sc, SP, (long)HEADS * SP * SP, (long)SP * SP,
                                        SP, SP, D_HEAD, 0.125f);
    }
    // 7. softmax (len 256)
    softmax_kernel<1><<<NB * HEADS * SP, 256>>>(sc, SP);
    // 8. attn = P @ V
    {
        dim3 ga(1, SP / GBM, NB * HEADS);
        bgemm_kernel<false><<<ga, 256>>>(sc, SP, (long)HEADS * SP * SP, (long)SP * SP,
                                         v, D_MODEL, (long)SP * D_MODEL, D_HEAD,
                                         attn, D_MODEL, (long)SP * D_MODEL, D_HEAD,
                                         SP, D_HEAD, SP, 1.f);
    }
    // 9. p1 = attn @ Wo + bo + prompt
    gemm_bias_kernel<<<gp, 256>>>(attn, pp_wo, pp_bo, prompt, p1, TOKP, D_MODEL, D_MODEL, 0);
    // 10. x = LN(p1 + prompt0)
    addln_kernel<<<TOKP, 256>>>(p1, prompt0, ln2g, ln2b, x);
    // 11. xi = LN(image + posi)
    addln_kernel<<<TOKI, 256>>>(image, posi, lnig, lnib, xi);
    // 12-14. cross-attn projections
    gemm_bias_kernel<<<gp, 256>>>(x,  pi_wq, pi_bq, nullptr, q, TOKP, D_MODEL, D_MODEL, 0);
    gemm_bias_kernel<<<gi, 256>>>(xi, pi_wk, pi_bk, nullptr, k, TOKI, D_MODEL, D_MODEL, 0);
    gemm_bias_kernel<<<gi, 256>>>(xi, pi_wv, pi_bv, nullptr, v, TOKI, D_MODEL, D_MODEL, 0);
    // 15. cross scores
    {
        dim3 gs(SI / GBN, SP / GBM, NB * HEADS);
        bgemm_kernel<true><<<gs, 256>>>(q, D_MODEL, (long)SP * D_MODEL, D_HEAD,
                                        k, D_MODEL, (long)SI * D_MODEL, D_HEAD,
                                        sc, SI, (long)HEADS * SP * SI, (long)SP * SI,
                                        SP, SI, D_HEAD, 0.125f);
    }
    // 16. softmax (len 1024)
    softmax_kernel<4><<<NB * HEADS * SP, 256>>>(sc, SI);
    // 17. attn = P @ V
    {
        dim3 ga(1, SP / GBM, NB * HEADS);
        bgemm_kernel<false><<<ga, 256>>>(sc, SI, (long)HEADS * SP * SI, (long)SP * SI,
                                         v, D_MODEL, (long)SI * D_MODEL, D_HEAD,
                                         attn, D_MODEL, (long)SP * D_MODEL, D_HEAD,
                                         SP, D_HEAD, SI, 1.f);
    }
    // 18. p2 = attn @ Wo + bo + p1
    gemm_bias_kernel<<<gp, 256>>>(attn, pi_wo, pi_bo, p1, p2, TOKP, D_MODEL, D_MODEL, 0);
    // 19. x = LN(p2 + prompt0)
    addln_kernel<<<TOKP, 256>>>(p2, prompt0, ln3g, ln3b, x);
    // 20. h = relu(x @ W1 + b1)
    gemm_bias_kernel<<<gp, 256>>>(x, ff_w1, ff_b1, nullptr, hbuf, TOKP, D_MODEL, D_MODEL, 1);
    // 21. out = h @ W2 + b2
    gemm_bias_kernel<<<gp, 256>>>(hbuf, ff_w2, ff_b2, nullptr, out, TOKP, D_MODEL, D_MODEL, 0);
}